// round 10
// baseline (speedup 1.0000x reference)
#include <cuda_runtime.h>
#include <cuda_bf16.h>
#include <mma.h>
#include <cstdint>
using namespace nvcuda;

#define BATCH   8
#define CIN     256
#define HWPX    4096
#define WIDTH   64
#define CR      64
#define GROUPS  32
#define GCH     8

// y = relu6(bn(conv1 x)) stored as bf16 hi/lo pairs (u32 = 2 px): 4.2MB each
__device__ __align__(16) unsigned int g_yh[(size_t)BATCH * CR * HWPX / 2];
__device__ __align__(16) unsigned int g_yl[(size_t)BATCH * CR * HWPX / 2];

typedef unsigned long long u64;
typedef unsigned int u32;

// ---------------- packed f32x2 helpers (K1) ----------------
__device__ __forceinline__ u64 ffma2(u64 a, u64 b, u64 c) {
    u64 d;
    asm("fma.rn.f32x2 %0, %1, %2, %3;" : "=l"(d) : "l"(a), "l"(b), "l"(c));
    return d;
}
__device__ __forceinline__ u64 pack2(float lo, float hi) {
    u64 d;
    asm("mov.b64 %0, {%1, %2};" : "=l"(d) : "f"(lo), "f"(hi));
    return d;
}
__device__ __forceinline__ float2 unpack2(u64 v) {
    float2 r;
    asm("mov.b64 {%0, %1}, %2;" : "=f"(r.x), "=f"(r.y) : "l"(v));
    return r;
}
// bf16x2 pack: low half = first arg
__device__ __forceinline__ u32 bf2(float lo, float hi) {
    u32 r;
    asm("cvt.rn.bf16x2.f32 %0, %1, %2;" : "=r"(r) : "f"(hi), "f"(lo));
    return r;
}
__device__ __forceinline__ float bflo(u32 p) { return __uint_as_float(p << 16); }
__device__ __forceinline__ float bfhi(u32 p) { return __uint_as_float(p & 0xFFFF0000u); }

// ---------------------------------------------------------------------------
// K1: conv1 (256->64) + BN + ReLU6 -> g_yh/g_yl (bf16 hi/lo)
// grid (32 px-tiles of 128, 8 batch), 256 threads, 2 CTAs/SM (round-7 core)
// ---------------------------------------------------------------------------
__global__ void __launch_bounds__(256, 2)
k1_conv1(const float* __restrict__ x,
         const float* __restrict__ w1, const float* __restrict__ b1,
         const float* __restrict__ gma, const float* __restrict__ bta,
         const float* __restrict__ mu,  const float* __restrict__ var)
{
    extern __shared__ float w1t[];                                     // [256][64]
    const ulonglong2* w1tv = reinterpret_cast<const ulonglong2*>(w1t); // [256][16]

    const int tid  = threadIdx.x;
    const int lane = tid & 31;
    const int cg   = tid >> 5;
    const int b    = blockIdx.y;
    const int px0  = blockIdx.x * 128;

    #pragma unroll 8
    for (int k = 0; k < 64; ++k) {
        int i  = tid + k * 256;
        int co = i & 63, ci = i >> 6;
        w1t[ci * 64 + co] = w1[co * 256 + ci];
    }
    __syncthreads();

    u64 acc[4][4];
    #pragma unroll
    for (int k = 0; k < 4; ++k)
        #pragma unroll
        for (int j = 0; j < 4; ++j) acc[k][j] = 0ull;

    const float4* x4 = reinterpret_cast<const float4*>(x + (size_t)b * CIN * HWPX + px0) + lane;

    float4 xv = x4[0];
    #pragma unroll 4
    for (int ci = 0; ci < 256; ++ci) {
        float4 xn = (ci < 255) ? x4[(ci + 1) * (HWPX / 4)] : xv;
        ulonglong2 wv0 = w1tv[ci * 16 + cg * 2];
        ulonglong2 wv1 = w1tv[ci * 16 + cg * 2 + 1];
        u64 xx0 = pack2(xv.x, xv.x);
        u64 xx1 = pack2(xv.y, xv.y);
        u64 xx2 = pack2(xv.z, xv.z);
        u64 xx3 = pack2(xv.w, xv.w);
        acc[0][0] = ffma2(wv0.x, xx0, acc[0][0]);
        acc[0][1] = ffma2(wv0.x, xx1, acc[0][1]);
        acc[0][2] = ffma2(wv0.x, xx2, acc[0][2]);
        acc[0][3] = ffma2(wv0.x, xx3, acc[0][3]);
        acc[1][0] = ffma2(wv0.y, xx0, acc[1][0]);
        acc[1][1] = ffma2(wv0.y, xx1, acc[1][1]);
        acc[1][2] = ffma2(wv0.y, xx2, acc[1][2]);
        acc[1][3] = ffma2(wv0.y, xx3, acc[1][3]);
        acc[2][0] = ffma2(wv1.x, xx0, acc[2][0]);
        acc[2][1] = ffma2(wv1.x, xx1, acc[2][1]);
        acc[2][2] = ffma2(wv1.x, xx2, acc[2][2]);
        acc[2][3] = ffma2(wv1.x, xx3, acc[2][3]);
        acc[3][0] = ffma2(wv1.y, xx0, acc[3][0]);
        acc[3][1] = ffma2(wv1.y, xx1, acc[3][1]);
        acc[3][2] = ffma2(wv1.y, xx2, acc[3][2]);
        acc[3][3] = ffma2(wv1.y, xx3, acc[3][3]);
        xv = xn;
    }

    uint2* yh2 = reinterpret_cast<uint2*>(g_yh);
    uint2* yl2 = reinterpret_cast<uint2*>(g_yl);
    #pragma unroll
    for (int k = 0; k < 4; ++k) {
        int co0 = cg * 8 + 2 * k, co1 = co0 + 1;
        float s0  = __ldg(&gma[co0]) * rsqrtf(__ldg(&var[co0]) + 1e-5f);
        float bb0 = fmaf(__ldg(&b1[co0]), s0, __ldg(&bta[co0]) - __ldg(&mu[co0]) * s0);
        float s1  = __ldg(&gma[co1]) * rsqrtf(__ldg(&var[co1]) + 1e-5f);
        float bb1 = fmaf(__ldg(&b1[co1]), s1, __ldg(&bta[co1]) - __ldg(&mu[co1]) * s1);
        float r0f[4], r1f[4];
        #pragma unroll
        for (int j = 0; j < 4; ++j) {
            float2 f = unpack2(acc[k][j]);
            r0f[j] = fminf(fmaxf(fmaf(f.x, s0, bb0), 0.f), 6.f);
            r1f[j] = fminf(fmaxf(fmaf(f.y, s1, bb1), 0.f), 6.f);
        }
        // hi/lo bf16 split, 4 px -> uint2
        {
            u32 hA = bf2(r0f[0], r0f[1]), hB = bf2(r0f[2], r0f[3]);
            u32 lA = bf2(r0f[0] - bflo(hA), r0f[1] - bfhi(hA));
            u32 lB = bf2(r0f[2] - bflo(hB), r0f[3] - bfhi(hB));
            size_t fi = ((size_t)(b * CR + co0) * HWPX + px0);
            yh2[(fi >> 2) + lane] = make_uint2(hA, hB);
            yl2[(fi >> 2) + lane] = make_uint2(lA, lB);
        }
        {
            u32 hA = bf2(r1f[0], r1f[1]), hB = bf2(r1f[2], r1f[3]);
            u32 lA = bf2(r1f[0] - bflo(hA), r1f[1] - bfhi(hA));
            u32 lB = bf2(r1f[2] - bflo(hB), r1f[3] - bfhi(hB));
            size_t fi = ((size_t)(b * CR + co1) * HWPX + px0);
            yh2[(fi >> 2) + lane] = make_uint2(hA, hB);
            yl2[(fi >> 2) + lane] = make_uint2(lA, lB);
        }
    }
}

// ---------------------------------------------------------------------------
// K2: conv2 via wmma bf16 (hi/lo, fp32 acc) + involution.
// grid (8 h-tiles of 8 rows, 32 groups, 8 batch) = 2048 CTAs, 256 threads.
// Per warp: 64 px (4 m16-tiles) x 32 taps (2 n16-tiles), K=64 in 4 chunks.
// smem: w2h[32x64]bf16 @0 (4KB) | w2l @4096 | xh 8x12x72 f32 @8192 (27648)
//       ys_hi [16cr][512px]bf16 @35840 (16KB) | ys_lo @52224 (16KB)
//       kern alias @35840: per warp [16px][36] f32 (2304B each)
// ---------------------------------------------------------------------------
#define SM_W2H  0
#define SM_W2L  4096
#define SM_XH   8192
#define SM_YSH  35840
#define SM_YSL  52224
#define SM_KERN 35840
#define SMEM_K2 68608

__global__ void __launch_bounds__(256, 2)
k2_fused(const float* __restrict__ x,
         const float* __restrict__ w2, const float* __restrict__ b2,
         float* __restrict__ out)
{
    extern __shared__ char sm[];
    __nv_bfloat16* w2h = reinterpret_cast<__nv_bfloat16*>(sm + SM_W2H);
    __nv_bfloat16* w2l = reinterpret_cast<__nv_bfloat16*>(sm + SM_W2L);
    float* xh = reinterpret_cast<float*>(sm + SM_XH);
    u32* ysh = reinterpret_cast<u32*>(sm + SM_YSH);
    u32* ysl = reinterpret_cast<u32*>(sm + SM_YSL);

    const int tid  = threadIdx.x;
    const int w    = tid >> 5;
    const int lane = tid & 31;
    const int b    = blockIdx.z;
    const int g    = blockIdx.y;
    const int h0   = blockIdx.x * 8;
    const int px0  = h0 * WIDTH;

    // ---- stage w2 hi/lo bf16: [32 taps(pad)][64 cr] ----
    for (int i = tid; i < 1024; i += 256) {      // u32 pairs: tap*32 + crpair
        int tap = i >> 5, cp = i & 31;
        float v0 = 0.f, v1 = 0.f;
        if (tap < 25) {
            const float* p = w2 + (size_t)(g * 25 + tap) * 64 + cp * 2;
            v0 = p[0]; v1 = p[1];
        }
        u32 h = bf2(v0, v1);
        u32 l = bf2(v0 - bflo(h), v1 - bfhi(h));
        reinterpret_cast<u32*>(w2h)[i] = h;
        reinterpret_cast<u32*>(w2l)[i] = l;
    }
    // ---- stage x halo: 8 ch x 12 rows x 68 cols, pitch 72 ----
    const float* xb = x + ((size_t)b * CIN + g * GCH) * HWPX;
    for (int i = tid; i < 8 * 12 * 68; i += 256) {
        int c   = i / 816;
        int rem = i - c * 816;
        int r2  = rem / 68;
        int cc  = rem - r2 * 68;
        int hy = h0 - 2 + r2, wx = cc - 2;
        float v = 0.f;
        if ((unsigned)hy < 64u && (unsigned)wx < 64u)
            v = xb[c * HWPX + hy * WIDTH + wx];
        xh[c * 864 + r2 * 72 + cc] = v;
    }

    // ---- conv2 GEMM: D[512px x 32taps] += Y[512x64] * W2^T[64x32], 3 passes ----
    wmma::fragment<wmma::accumulator, 16, 16, 16, float> d[4][2];
    #pragma unroll
    for (int m = 0; m < 4; ++m) {
        wmma::fill_fragment(d[m][0], 0.0f);
        wmma::fill_fragment(d[m][1], 0.0f);
    }

    const uint4* yh4 = reinterpret_cast<const uint4*>(g_yh);
    const uint4* yl4 = reinterpret_cast<const uint4*>(g_yl);
    const size_t ybase = ((size_t)b * CR * HWPX + px0) >> 3;   // uint4 units

    for (int kc = 0; kc < 4; ++kc) {
        __syncthreads();   // prior mma readers done (first: staging ordered)
        for (int i = tid; i < 1024; i += 256) {    // [16 rows][64 uint4]
            int row = i >> 6, c16 = i & 63;
            size_t gi = ybase + (size_t)(kc * 16 + row) * (HWPX / 8) + c16;
            reinterpret_cast<uint4*>(ysh)[i] = yh4[gi];
            reinterpret_cast<uint4*>(ysl)[i] = yl4[gi];
        }
        __syncthreads();

        wmma::fragment<wmma::matrix_b, 16, 16, 16, __nv_bfloat16, wmma::col_major> bh[2], bl[2];
        #pragma unroll
        for (int n = 0; n < 2; ++n) {
            wmma::load_matrix_sync(bh[n], w2h + n * 16 * 64 + kc * 16, 64);
            wmma::load_matrix_sync(bl[n], w2l + n * 16 * 64 + kc * 16, 64);
        }
        #pragma unroll
        for (int m = 0; m < 4; ++m) {
            wmma::fragment<wmma::matrix_a, 16, 16, 16, __nv_bfloat16, wmma::col_major> ah, al;
            const __nv_bfloat16* ap = reinterpret_cast<const __nv_bfloat16*>(ysh) + w * 64 + m * 16;
            const __nv_bfloat16* lp = reinterpret_cast<const __nv_bfloat16*>(ysl) + w * 64 + m * 16;
            wmma::load_matrix_sync(ah, ap, 512);
            wmma::load_matrix_sync(al, lp, 512);
            #pragma unroll
            for (int n = 0; n < 2; ++n) {
                wmma::mma_sync(d[m][n], ah, bh[n], d[m][n]);
                wmma::mma_sync(d[m][n], ah, bl[n], d[m][n]);
                wmma::mma_sync(d[m][n], al, bh[n], d[m][n]);
            }
        }
    }
    __syncthreads();   // ys region dead -> kern alias safe

    // ---- involution: per m-tile, kern roundtrip via smem ----
    float* ks = reinterpret_cast<float*>(sm + SM_KERN) + w * 576;   // [16][36]
    const int pxl  = lane >> 1;
    const int half = lane & 1;

    #pragma unroll
    for (int m = 0; m < 4; ++m) {
        wmma::store_matrix_sync(ks,      d[m][0], 36, wmma::mem_row_major);
        wmma::store_matrix_sync(ks + 16, d[m][1], 36, wmma::mem_row_major);
        __syncwarp();

        float kt[25];
        #pragma unroll
        for (int t = 0; t < 25; ++t)
            kt[t] = ks[pxl * 36 + t] + __ldg(b2 + g * 25 + t);

        const int pxt = w * 64 + m * 16 + pxl;       // 0..511 within tile
        const int rr  = pxt >> 6, col = pxt & 63;
        float o[4] = {0.f, 0.f, 0.f, 0.f};
        #pragma unroll
        for (int ti = 0; ti < 5; ++ti) {
            #pragma unroll
            for (int tj = 0; tj < 5; ++tj) {
                float kv = kt[ti * 5 + tj];
                #pragma unroll
                for (int j = 0; j < 4; ++j) {
                    int c = half * 4 + j;
                    o[j] = fmaf(kv, xh[c * 864 + (rr + ti) * 72 + col + tj], o[j]);
                }
            }
        }
        float* ob = out + ((size_t)b * CIN + g * GCH + half * 4) * HWPX + px0 + pxt;
        #pragma unroll
        for (int j = 0; j < 4; ++j) ob[(size_t)j * HWPX] = o[j];
        __syncwarp();   // before next m-tile overwrites ks
    }
}

// ---------------------------------------------------------------------------
extern "C" void kernel_launch(void* const* d_in, const int* in_sizes, int n_in,
                              void* d_out, int out_size)
{
    const float* x   = (const float*)d_in[0];
    const float* w1  = (const float*)d_in[1];
    const float* b1  = (const float*)d_in[2];
    const float* gma = (const float*)d_in[3];
    const float* bta = (const float*)d_in[4];
    const float* mu  = (const float*)d_in[5];
    const float* var = (const float*)d_in[6];
    const float* w2  = (const float*)d_in[7];
    const float* b2  = (const float*)d_in[8];
    float* out = (float*)d_out;

    const int SMEM1 = 65536;
    cudaFuncSetAttribute(k1_conv1, cudaFuncAttributeMaxDynamicSharedMemorySize, SMEM1);
    cudaFuncSetAttribute(k2_fused, cudaFuncAttributeMaxDynamicSharedMemorySize, SMEM_K2);

    k1_conv1<<<dim3(32, 8), 256, SMEM1>>>(x, w1, b1, gma, bta, mu, var);
    k2_fused<<<dim3(8, 32, 8), 256, SMEM_K2>>>(x, w2, b2, out);
}

// round 11
// speedup vs baseline: 1.6047x; 1.6047x over previous
#include <cuda_runtime.h>
#include <cstdint>

#define BATCH   8
#define CIN     256
#define HWPX    4096
#define WIDTH   64
#define CR      64
#define GROUPS  32
#define GCH     8

// intermediate y = relu6(bn(conv1(x)))  : [B][64][4096] = 8.4 MB (L2-resident)
__device__ __align__(16) float g_y[(size_t)BATCH * CR * HWPX];

typedef unsigned long long u64;

// ---------------- packed f32x2 helpers ----------------
__device__ __forceinline__ u64 ffma2(u64 a, u64 b, u64 c) {
    u64 d;
    asm("fma.rn.f32x2 %0, %1, %2, %3;" : "=l"(d) : "l"(a), "l"(b), "l"(c));
    return d;
}
__device__ __forceinline__ u64 pack2(float lo, float hi) {
    u64 d;
    asm("mov.b64 %0, {%1, %2};" : "=l"(d) : "f"(lo), "f"(hi));
    return d;
}
__device__ __forceinline__ float2 unpack2(u64 v) {
    float2 r;
    asm("mov.b64 {%0, %1}, %2;" : "=f"(r.x), "=f"(r.y) : "l"(v));
    return r;
}

// ---------------------------------------------------------------------------
// K1: conv1 (256->64) + BN + ReLU6 -> g_y
// grid (32 px-tiles of 128, 8 batch) = 256 CTAs, 256 threads, 3 CTAs/SM
// smem: w1t [256ci][64co] transposed (64KB)
// warp = 32 lanes x float4 = fully-coalesced 512B LDG per channel
// thread: 1 quad x 8 co (acc 4x4 u64), lookahead-1 on x
// ---------------------------------------------------------------------------
__global__ void __launch_bounds__(256, 3)
k1_conv1(const float* __restrict__ x,
         const float* __restrict__ w1, const float* __restrict__ b1,
         const float* __restrict__ gma, const float* __restrict__ bta,
         const float* __restrict__ mu,  const float* __restrict__ var)
{
    extern __shared__ float w1t[];                                     // [256][64]
    const ulonglong2* w1tv = reinterpret_cast<const ulonglong2*>(w1t); // [256][16]

    const int tid  = threadIdx.x;
    const int lane = tid & 31;         // px quad (32 quads = 128 px)
    const int cg   = tid >> 5;         // co group: 8 co
    const int b    = blockIdx.y;
    const int px0  = blockIdx.x * 128;

    #pragma unroll 8
    for (int k = 0; k < 64; ++k) {
        int i  = tid + k * 256;
        int co = i & 63, ci = i >> 6;
        w1t[ci * 64 + co] = w1[co * 256 + ci];
    }
    __syncthreads();

    u64 acc[4][4];
    #pragma unroll
    for (int k = 0; k < 4; ++k)
        #pragma unroll
        for (int j = 0; j < 4; ++j) acc[k][j] = 0ull;

    const float4* x4 = reinterpret_cast<const float4*>(x + (size_t)b * CIN * HWPX + px0) + lane;

    float4 xv = x4[0];
    #pragma unroll 4
    for (int ci = 0; ci < 256; ++ci) {
        float4 xn = (ci < 255) ? x4[(ci + 1) * (HWPX / 4)] : xv;
        ulonglong2 wv0 = w1tv[ci * 16 + cg * 2];
        ulonglong2 wv1 = w1tv[ci * 16 + cg * 2 + 1];
        u64 xx0 = pack2(xv.x, xv.x);
        u64 xx1 = pack2(xv.y, xv.y);
        u64 xx2 = pack2(xv.z, xv.z);
        u64 xx3 = pack2(xv.w, xv.w);
        acc[0][0] = ffma2(wv0.x, xx0, acc[0][0]);
        acc[0][1] = ffma2(wv0.x, xx1, acc[0][1]);
        acc[0][2] = ffma2(wv0.x, xx2, acc[0][2]);
        acc[0][3] = ffma2(wv0.x, xx3, acc[0][3]);
        acc[1][0] = ffma2(wv0.y, xx0, acc[1][0]);
        acc[1][1] = ffma2(wv0.y, xx1, acc[1][1]);
        acc[1][2] = ffma2(wv0.y, xx2, acc[1][2]);
        acc[1][3] = ffma2(wv0.y, xx3, acc[1][3]);
        acc[2][0] = ffma2(wv1.x, xx0, acc[2][0]);
        acc[2][1] = ffma2(wv1.x, xx1, acc[2][1]);
        acc[2][2] = ffma2(wv1.x, xx2, acc[2][2]);
        acc[2][3] = ffma2(wv1.x, xx3, acc[2][3]);
        acc[3][0] = ffma2(wv1.y, xx0, acc[3][0]);
        acc[3][1] = ffma2(wv1.y, xx1, acc[3][1]);
        acc[3][2] = ffma2(wv1.y, xx2, acc[3][2]);
        acc[3][3] = ffma2(wv1.y, xx3, acc[3][3]);
        xv = xn;
    }

    float4* y4 = reinterpret_cast<float4*>(g_y + (size_t)b * CR * HWPX + px0) + lane;
    #pragma unroll
    for (int k = 0; k < 4; ++k) {
        int co0 = cg * 8 + 2 * k, co1 = co0 + 1;
        float s0  = __ldg(&gma[co0]) * rsqrtf(__ldg(&var[co0]) + 1e-5f);
        float bb0 = fmaf(__ldg(&b1[co0]), s0, __ldg(&bta[co0]) - __ldg(&mu[co0]) * s0);
        float s1  = __ldg(&gma[co1]) * rsqrtf(__ldg(&var[co1]) + 1e-5f);
        float bb1 = fmaf(__ldg(&b1[co1]), s1, __ldg(&bta[co1]) - __ldg(&mu[co1]) * s1);
        float4 r0, r1;
        float* r0f = reinterpret_cast<float*>(&r0);
        float* r1f = reinterpret_cast<float*>(&r1);
        #pragma unroll
        for (int j = 0; j < 4; ++j) {
            float2 f = unpack2(acc[k][j]);
            r0f[j] = fminf(fmaxf(fmaf(f.x, s0, bb0), 0.f), 6.f);
            r1f[j] = fminf(fmaxf(fmaf(f.y, s1, bb1), 0.f), 6.f);
        }
        y4[(size_t)co0 * (HWPX / 4)] = r0;
        y4[(size_t)co1 * (HWPX / 4)] = r1;
    }
}

// ---------------------------------------------------------------------------
// K2: fused conv2 + involution, SINGLE pass over all 25 taps (round-7, 129us).
// grid (8 h-tiles of 8 rows, 32 groups, 8 batch) = 2048 CTAs, 256 th, 2 CTAs/SM
// Thread owns a pixel PAIR (px = 2*tid): ka = [5 rows][3 tap-pairs] u64 per px.
// smem: xh [8ch][12r][72c] f32 = 27648B | w2p [64cr][32f] = 8192B
// ---------------------------------------------------------------------------
__global__ void __launch_bounds__(256, 2)
k2_fused(const float* __restrict__ x,
         const float* __restrict__ w2, const float* __restrict__ b2,
         float* __restrict__ out)
{
    extern __shared__ char smraw[];
    float* xh  = reinterpret_cast<float*>(smraw);                 // 27648 B
    float* w2p = reinterpret_cast<float*>(smraw + 27648);         // 8192 B

    const int tid = threadIdx.x;
    const int b   = blockIdx.z;
    const int g   = blockIdx.y;
    const int h0  = blockIdx.x * 8;
    const int px0 = h0 * WIDTH;
    const int rr  = tid >> 5;        // tile row 0..7
    const int col = (tid & 31) * 2;  // column of px0 of the pair

    // ---- stage x halo: 8 ch x 12 rows x 68 cols, pitch 72 ----
    const float* xb = x + ((size_t)b * CIN + g * GCH) * HWPX;
    for (int i = tid; i < 8 * 12 * 68; i += 256) {
        int c   = i / 816;
        int rem = i - c * 816;
        int r2  = rem / 68;
        int cc  = rem - r2 * 68;
        int hy = h0 - 2 + r2, wx = cc - 2;
        float v = 0.f;
        if ((unsigned)hy < 64u && (unsigned)wx < 64u)
            v = xb[c * HWPX + hy * WIDTH + wx];
        xh[c * 864 + r2 * 72 + cc] = v;
    }
    // ---- stage w2p[cr][ti*6+j] = w2[(g*25+5ti+j)*64+cr], j=5 & tail = 0 ----
    for (int i = tid; i < 64 * 32; i += 256) {
        int cr  = i >> 5;
        int rem = i & 31;
        int ti  = rem / 6;
        int j   = rem - ti * 6;
        float v = (ti < 5 && j < 5) ? w2[(size_t)(g * 25 + ti * 5 + j) * 64 + cr] : 0.f;
        w2p[cr * 32 + rem] = v;
    }
    __syncthreads();

    // ---- ka seeded with bias: pairs {tap 5ti+2k, 5ti+2k+1}, k=2 -> {tap+4, 0}
    u64 kaA[5][3], kaB[5][3];
    #pragma unroll
    for (int ti = 0; ti < 5; ++ti) {
        float t0 = __ldg(b2 + g * 25 + ti * 5 + 0);
        float t1 = __ldg(b2 + g * 25 + ti * 5 + 1);
        float t2 = __ldg(b2 + g * 25 + ti * 5 + 2);
        float t3 = __ldg(b2 + g * 25 + ti * 5 + 3);
        float t4 = __ldg(b2 + g * 25 + ti * 5 + 4);
        kaA[ti][0] = pack2(t0, t1); kaB[ti][0] = kaA[ti][0];
        kaA[ti][1] = pack2(t2, t3); kaB[ti][1] = kaA[ti][1];
        kaA[ti][2] = pack2(t4, 0.f); kaB[ti][2] = kaA[ti][2];
    }

    // ---- conv2: single pass over 64 reduced channels ----
    const u64* yp = reinterpret_cast<const u64*>(g_y + (size_t)b * CR * HWPX + px0) + tid;
    u64 ybuf[4];
    #pragma unroll
    for (int i = 0; i < 4; ++i) ybuf[i] = yp[(size_t)i * (HWPX / 2)];

    #pragma unroll 4
    for (int cr = 0; cr < 64; ++cr) {
        u64 yv = ybuf[cr & 3];
        if (cr < 60) ybuf[cr & 3] = yp[(size_t)(cr + 4) * (HWPX / 2)];
        float2 yf = unpack2(yv);
        u64 y00 = pack2(yf.x, yf.x);
        u64 y11 = pack2(yf.y, yf.y);

        const ulonglong2* wr = reinterpret_cast<const ulonglong2*>(w2p + cr * 32);
        ulonglong2 wv[8];
        #pragma unroll
        for (int m = 0; m < 8; ++m) wv[m] = wr[m];

        #pragma unroll
        for (int ti = 0; ti < 5; ++ti) {
            #pragma unroll
            for (int k = 0; k < 3; ++k) {
                int m = ti * 3 + k;                              // u64 index 0..14
                u64 w = (m & 1) ? wv[m >> 1].y : wv[m >> 1].x;   // {w[2m], w[2m+1]}
                kaA[ti][k] = ffma2(w, y00, kaA[ti][k]);
                kaB[ti][k] = ffma2(w, y11, kaB[ti][k]);
            }
        }
    }

    // ---- involution + store (per channel, fold pair lanes at the end) ----
    #pragma unroll
    for (int c = 0; c < 8; ++c) {
        u64 oA = 0ull, oB = 0ull;
        #pragma unroll
        for (int ti = 0; ti < 5; ++ti) {
            const float2* xr =
                reinterpret_cast<const float2*>(xh + c * 864 + (rr + ti) * 72 + col);
            float2 f0 = xr[0], f1 = xr[1], f2 = xr[2];    // w[0..5]
            u64 q0 = pack2(f0.x, f0.y);   // px0: {w0,w1}
            u64 q1 = pack2(f1.x, f1.y);   //      {w2,w3}
            u64 q2 = pack2(f2.x, f2.y);   //      {w4, ignored (ka pad=0)}
            u64 s0 = pack2(f0.y, f1.x);   // px1: {w1,w2}
            u64 s1 = pack2(f1.y, f2.x);   //      {w3,w4}
            u64 s2 = pack2(f2.y, f2.y);   //      {w5, ignored}
            oA = ffma2(kaA[ti][0], q0, oA);
            oA = ffma2(kaA[ti][1], q1, oA);
            oA = ffma2(kaA[ti][2], q2, oA);
            oB = ffma2(kaB[ti][0], s0, oB);
            oB = ffma2(kaB[ti][1], s1, oB);
            oB = ffma2(kaB[ti][2], s2, oB);
        }
        float2 a = unpack2(oA);
        float2 bb = unpack2(oB);
        float2 rv;
        rv.x = a.x + a.y;    // px0 = even taps + odd taps
        rv.y = bb.x + bb.y;  // px1
        *reinterpret_cast<float2*>(
            out + ((size_t)b * CIN + g * GCH + c) * HWPX + px0 + rr * WIDTH + col) = rv;
    }
}

// ---------------------------------------------------------------------------
extern "C" void kernel_launch(void* const* d_in, const int* in_sizes, int n_in,
                              void* d_out, int out_size)
{
    const float* x   = (const float*)d_in[0];
    const float* w1  = (const float*)d_in[1];
    const float* b1  = (const float*)d_in[2];
    const float* gma = (const float*)d_in[3];
    const float* bta = (const float*)d_in[4];
    const float* mu  = (const float*)d_in[5];
    const float* var = (const float*)d_in[6];
    const float* w2  = (const float*)d_in[7];
    const float* b2  = (const float*)d_in[8];
    float* out = (float*)d_out;

    const int SMEM1 = 65536;          // w1t
    const int SMEM2 = 27648 + 8192;   // 35840 B
    cudaFuncSetAttribute(k1_conv1, cudaFuncAttributeMaxDynamicSharedMemorySize, SMEM1);
    cudaFuncSetAttribute(k2_fused, cudaFuncAttributeMaxDynamicSharedMemorySize, SMEM2);

    k1_conv1<<<dim3(32, 8), 256, SMEM1>>>(x, w1, b1, gma, bta, mu, var);
    k2_fused<<<dim3(8, 32, 8), 256, SMEM2>>>(x, w2, b2, out);
}